// round 5
// baseline (speedup 1.0000x reference)
#include <cuda_runtime.h>
#include <stdint.h>

// ---------------------------------------------------------------------------
// Problem constants
// ---------------------------------------------------------------------------
static const int kB  = 1024;   // batch
static const int kIN = 784;    // input dim
static const int kE  = 256;    // embed dim
static const int kC  = 10;     // classes
static const int kAD = 3;      // ADIM
static const int kBR = 4;      // BRAIN
static const int kNB = 64;     // BRAIN^ADIM blocks
static const int kJ  = 4;      // NJUMPS

// ---------------------------------------------------------------------------
// Scratch (device globals -- no cudaMalloc allowed)
// ---------------------------------------------------------------------------
__device__ float g_state[kB * kE];
__device__ float g_init [kB * kE];
__device__ float g_new  [kB * kE];
__device__ float g_fin  [kB * kE];
__device__ float g_h    [kB * kE];
__device__ int   g_nidx [kB];
__device__ int   g_done [kB];
__device__ int   g_off  [kNB + 1];
__device__ int   g_order[kB];

// ---------------------------------------------------------------------------
// Threefry-2x32-20 (KAT: key(0,0) ctr(0,0) -> 0x6b200159, 0x99ba4efe)
// ---------------------------------------------------------------------------
__host__ __device__ inline void tf2x32(uint32_t k0, uint32_t k1,
                                       uint32_t x0, uint32_t x1,
                                       uint32_t* o0, uint32_t* o1)
{
    uint32_t ks2 = k0 ^ k1 ^ 0x1BD11BDAu;
    x0 += k0; x1 += k1;
#define TF_ROT(v, d) (((v) << (d)) | ((v) >> (32 - (d))))
#define TF_R4(a, b, c, d)                                    \
    { x0 += x1; x1 = TF_ROT(x1, a); x1 ^= x0;                \
      x0 += x1; x1 = TF_ROT(x1, b); x1 ^= x0;                \
      x0 += x1; x1 = TF_ROT(x1, c); x1 ^= x0;                \
      x0 += x1; x1 = TF_ROT(x1, d); x1 ^= x0; }
    TF_R4(13, 15, 26, 6)   x0 += k1;  x1 += ks2 + 1u;
    TF_R4(17, 29, 16, 24)  x0 += ks2; x1 += k0  + 2u;
    TF_R4(13, 15, 26, 6)   x0 += k0;  x1 += k1  + 3u;
    TF_R4(17, 29, 16, 24)  x0 += k1;  x1 += ks2 + 4u;
    TF_R4(13, 15, 26, 6)   x0 += ks2; x1 += k0  + 5u;
#undef TF_R4
#undef TF_ROT
    *o0 = x0; *o1 = x1;
}

// ---------------------------------------------------------------------------
// Generic tiled GEMM: C = act(A[MxK] @ W[KxN] + bias), optional 2nd copy.
// BM=32, BN=64, BK=16, 256 threads, 2x4 per thread. K % 16 == 0 required.
// ---------------------------------------------------------------------------
template<bool RELU, bool COPY2>
__global__ void gemm_kernel(const float* __restrict__ A,
                            const float* __restrict__ W,
                            const float* __restrict__ bias,
                            float* __restrict__ C,
                            float* __restrict__ C2,
                            int M, int K, int Nn)
{
    __shared__ float As[16][33];   // [kk][row], padded vs bank conflicts
    __shared__ float Ws[16][64];   // [kk][col]
    const int t  = threadIdx.x;
    const int tx = t & 15;
    const int ty = t >> 4;
    const int row0 = blockIdx.y * 32;
    const int col0 = blockIdx.x * 64;
    float acc[2][4] = {{0.f,0.f,0.f,0.f},{0.f,0.f,0.f,0.f}};

    for (int k0 = 0; k0 < K; k0 += 16) {
        if (t < 128) {
            int r  = t >> 2;           // 0..31
            int kk = (t & 3) * 4;      // 0,4,8,12
            float4 v = *(const float4*)(A + (size_t)(row0 + r) * K + k0 + kk);
            As[kk + 0][r] = v.x;
            As[kk + 1][r] = v.y;
            As[kk + 2][r] = v.z;
            As[kk + 3][r] = v.w;
        }
        {
            int kk = t >> 4;           // 0..15
            int c  = (t & 15) * 4;     // 0..60
            *(float4*)&Ws[kk][c] =
                *(const float4*)(W + (size_t)(k0 + kk) * Nn + col0 + c);
        }
        __syncthreads();
        #pragma unroll
        for (int kk = 0; kk < 16; kk++) {
            float a0 = As[kk][ty * 2 + 0];
            float a1 = As[kk][ty * 2 + 1];
            float4 b4 = *(const float4*)&Ws[kk][tx * 4];
            acc[0][0] = fmaf(a0, b4.x, acc[0][0]);
            acc[0][1] = fmaf(a0, b4.y, acc[0][1]);
            acc[0][2] = fmaf(a0, b4.z, acc[0][2]);
            acc[0][3] = fmaf(a0, b4.w, acc[0][3]);
            acc[1][0] = fmaf(a1, b4.x, acc[1][0]);
            acc[1][1] = fmaf(a1, b4.y, acc[1][1]);
            acc[1][2] = fmaf(a1, b4.z, acc[1][2]);
            acc[1][3] = fmaf(a1, b4.w, acc[1][3]);
        }
        __syncthreads();
    }

    float4 bv = *(const float4*)(bias + col0 + tx * 4);
    #pragma unroll
    for (int i = 0; i < 2; i++) {
        float4 o;
        o.x = acc[i][0] + bv.x;
        o.y = acc[i][1] + bv.y;
        o.z = acc[i][2] + bv.z;
        o.w = acc[i][3] + bv.w;
        if (RELU) {
            o.x = fmaxf(o.x, 0.f); o.y = fmaxf(o.y, 0.f);
            o.z = fmaxf(o.z, 0.f); o.w = fmaxf(o.w, 0.f);
        }
        size_t off = (size_t)(row0 + ty * 2 + i) * Nn + col0 + tx * 4;
        *(float4*)(C + off) = o;
        if (COPY2) *(float4*)(C2 + off) = o;
    }
}

// ---------------------------------------------------------------------------
// Group samples by current block index: counts -> prefix -> scatter.
// Single CTA of kB threads.
// ---------------------------------------------------------------------------
__global__ void group_kernel()
{
    __shared__ int scnt[kNB];
    __shared__ int soff[kNB + 1];
    const int t = threadIdx.x;
    if (t < kNB) scnt[t] = 0;
    __syncthreads();
    const int n = g_nidx[t];
    atomicAdd(&scnt[n], 1);
    __syncthreads();
    if (t == 0) {
        int a = 0;
        for (int i = 0; i < kNB; i++) { soff[i] = a; a += scnt[i]; }
        soff[kNB] = a;
    }
    __syncthreads();
    if (t <= kNB) g_off[t] = soff[t];
    if (t < kNB)  scnt[t] = soff[t];   // reuse as cursors
    __syncthreads();
    int pos = atomicAdd(&scnt[n], 1);
    g_order[pos] = t;
}

// ---------------------------------------------------------------------------
// Grouped block MLP: for samples assigned to block n:
//   h1 = relu(state @ W1[n] + b1[n]); h2 = relu(h1 @ W2[n] + b2[n])
//   out = h2 / (||state|| + 1e-6)  (+ initial_state if addInit)
// grid (kNB, 16), 256 threads, 8 samples per tile.
// ---------------------------------------------------------------------------
__global__ void block_step_kernel(const float* __restrict__ W1,
                                  const float* __restrict__ b1,
                                  const float* __restrict__ W2,
                                  const float* __restrict__ b2,
                                  const float* __restrict__ st,
                                  float* __restrict__ outp,
                                  const float* __restrict__ ini,
                                  int addInit)
{
    const int TS = 8;
    __shared__ float sst[TS][kE];
    __shared__ float sh [TS][kE];
    __shared__ float snorm[TS];
    __shared__ int   sids[TS];
    const int n    = blockIdx.x;
    const int t    = threadIdx.x;
    const int wid  = t >> 5;
    const int lane = t & 31;
    const int base = g_off[n];
    const int cnt  = g_off[n + 1] - base;

    for (int tile = blockIdx.y; tile * TS < cnt; tile += gridDim.y) {
        const int m = min(TS, cnt - tile * TS);
        if (t < TS) sids[t] = (t < m) ? g_order[base + tile * TS + t] : 0;
        __syncthreads();
        #pragma unroll
        for (int s = 0; s < TS; s++)
            sst[s][t] = (s < m) ? st[(size_t)sids[s] * kE + t] : 0.0f;
        __syncthreads();
        {   // per-sample L2 norm of input state (warp per sample)
            const int s = wid;  // 8 warps == TS
            float v = 0.f;
            #pragma unroll
            for (int q = 0; q < kE / 32; q++) {
                float x = sst[s][lane + 32 * q];
                v = fmaf(x, x, v);
            }
            #pragma unroll
            for (int o = 16; o; o >>= 1) v += __shfl_down_sync(0xffffffffu, v, o);
            if (lane == 0) snorm[s] = sqrtf(v) + 1e-6f;
        }
        __syncthreads();

        float acc[TS];
        {   // layer 1
            float bv = b1[n * kE + t];
            #pragma unroll
            for (int s = 0; s < TS; s++) acc[s] = bv;
            const float* w = W1 + (size_t)n * kE * kE + t;
            for (int e = 0; e < kE; e += 4) {
                float w0  = w[(size_t)(e + 0) * kE];
                float w1v = w[(size_t)(e + 1) * kE];
                float w2v = w[(size_t)(e + 2) * kE];
                float w3v = w[(size_t)(e + 3) * kE];
                #pragma unroll
                for (int s = 0; s < TS; s++) {
                    float4 sv = *(const float4*)&sst[s][e];
                    acc[s] = fmaf(sv.x, w0,  acc[s]);
                    acc[s] = fmaf(sv.y, w1v, acc[s]);
                    acc[s] = fmaf(sv.z, w2v, acc[s]);
                    acc[s] = fmaf(sv.w, w3v, acc[s]);
                }
            }
            #pragma unroll
            for (int s = 0; s < TS; s++) sh[s][t] = fmaxf(acc[s], 0.f);
        }
        __syncthreads();
        {   // layer 2
            float bv = b2[n * kE + t];
            #pragma unroll
            for (int s = 0; s < TS; s++) acc[s] = bv;
            const float* w = W2 + (size_t)n * kE * kE + t;
            for (int e = 0; e < kE; e += 4) {
                float w0  = w[(size_t)(e + 0) * kE];
                float w1v = w[(size_t)(e + 1) * kE];
                float w2v = w[(size_t)(e + 2) * kE];
                float w3v = w[(size_t)(e + 3) * kE];
                #pragma unroll
                for (int s = 0; s < TS; s++) {
                    float4 sv = *(const float4*)&sh[s][e];
                    acc[s] = fmaf(sv.x, w0,  acc[s]);
                    acc[s] = fmaf(sv.y, w1v, acc[s]);
                    acc[s] = fmaf(sv.z, w2v, acc[s]);
                    acc[s] = fmaf(sv.w, w3v, acc[s]);
                }
            }
        }
        for (int s = 0; s < m; s++) {
            float val = fmaxf(acc[s], 0.f) / snorm[s];
            size_t off = (size_t)sids[s] * kE + t;
            if (addInit) val += ini[off];
            outp[off] = val;
        }
        __syncthreads();
    }
}

// ---------------------------------------------------------------------------
// Address head: logits = h @ at0_W2 + b2, add exact JAX gumbel noise
// (partitionable threefry: bits[i] = o0^o1 of threefry(key, (0, i))),
// argmax per digit -> block index; gated state/nidx/done update.
// One warp per sample; h = relu(src_state @ at0_W1 + b1) precomputed in g_h.
// ---------------------------------------------------------------------------
__global__ void addr_kernel(const float* __restrict__ h,
                            const float* __restrict__ W2,
                            const float* __restrict__ b2,
                            uint32_t k0, uint32_t k1, int isJump)
{
    const int wid  = threadIdx.x >> 5;
    const int lane = threadIdx.x & 31;
    const int b = blockIdx.x * (blockDim.x >> 5) + wid;
    if (b >= kB) return;
    const unsigned fm = 0xffffffffu;
    const int KOUT = kAD * kBR;   // 12

    float hr[kE / 32];
    #pragma unroll
    for (int q = 0; q < kE / 32; q++) hr[q] = h[(size_t)b * kE + lane + 32 * q];

    float zmine = 0.0f;
    #pragma unroll
    for (int k = 0; k < KOUT; k++) {
        float sum = 0.0f;
        #pragma unroll
        for (int q = 0; q < kE / 32; q++)
            sum = fmaf(hr[q], W2[(size_t)(lane + 32 * q) * KOUT + k], sum);
        #pragma unroll
        for (int o = 16; o; o >>= 1) sum += __shfl_down_sync(fm, sum, o);
        float v = __shfl_sync(fm, sum, 0);
        if (lane == k) zmine = v + b2[k];
    }

    // exact JAX gumbel noise (jax_threefry_partitionable=True path):
    // element i of the (B, ADIM, BRAIN) uniform draw uses 64-bit counter i:
    //   (o0,o1) = threefry2x32(key, (i>>32, i&0xffffffff));  bits = o0 ^ o1
    if (lane < KOUT) {
        uint32_t idx = (uint32_t)(b * KOUT + lane);   // < 12288, hi word = 0
        uint32_t y0, y1;
        tf2x32(k0, k1, 0u, idx, &y0, &y1);
        uint32_t bits = y0 ^ y1;
        float u = __uint_as_float((bits >> 9) | 0x3f800000u) - 1.0f;
        const float minv = 1e-6f;
        const float span = 0.999999f - 1e-6f;   // fp32, same as JAX
        float vv = u * span + minv;
        vv = fmaxf(minv, vv);
        // fp64 log: immune to fast-math logf, ~1e-16 accurate
        zmine += (float)(-log(-log((double)vv)));
    }

    // gather 12 perturbed logits, argmax per digit (first-index tie rule via >)
    float zv[12];
    #pragma unroll
    for (int k = 0; k < KOUT; k++) zv[k] = __shfl_sync(fm, zmine, k);

    int done_b = isJump ? g_done[b] : 0;

    if (lane == 0) {
        int n_val = 0;
        #pragma unroll
        for (int d = 0; d < kAD; d++) {
            int bi = 0;
            float bvv = zv[d * kBR];
            #pragma unroll
            for (int c = 1; c < kBR; c++) {
                float x = zv[d * kBR + c];
                if (x > bvv) { bvv = x; bi = c; }
            }
            n_val = n_val * kBR + bi;
        }
        if (!isJump) {
            g_nidx[b] = n_val;
            g_done[b] = 0;
        } else if (!done_b) {
            g_nidx[b] = n_val;
            if (n_val == 0) g_done[b] = 1;
        }
    }

    if (isJump && !done_b) {
        // commit new_state for active samples
        #pragma unroll
        for (int q = 0; q < kE / 32; q++) {
            size_t off = (size_t)b * kE + lane + 32 * q;
            g_state[off] = g_new[off];
        }
    }
}

// ---------------------------------------------------------------------------
// Output head: out = h @ out_W2 + out_b2 (256 -> 10). One warp per sample.
// ---------------------------------------------------------------------------
__global__ void out_kernel(const float* __restrict__ h,
                           const float* __restrict__ W2,
                           const float* __restrict__ b2,
                           float* __restrict__ outp)
{
    const int wid  = threadIdx.x >> 5;
    const int lane = threadIdx.x & 31;
    const int b = blockIdx.x * (blockDim.x >> 5) + wid;
    if (b >= kB) return;
    const unsigned fm = 0xffffffffu;

    float hr[kE / 32];
    #pragma unroll
    for (int q = 0; q < kE / 32; q++) hr[q] = h[(size_t)b * kE + lane + 32 * q];

    #pragma unroll
    for (int c = 0; c < kC; c++) {
        float sum = 0.0f;
        #pragma unroll
        for (int q = 0; q < kE / 32; q++)
            sum = fmaf(hr[q], W2[(size_t)(lane + 32 * q) * kC + c], sum);
        #pragma unroll
        for (int o = 16; o; o >>= 1) sum += __shfl_down_sync(fm, sum, o);
        if (lane == 0) outp[(size_t)b * kC + c] = sum + b2[c];
    }
}

// ---------------------------------------------------------------------------
// Launch
// ---------------------------------------------------------------------------
extern "C" void kernel_launch(void* const* d_in, const int* in_sizes, int n_in,
                              void* d_out, int out_size)
{
    (void)in_sizes; (void)n_in; (void)out_size;
    const float* x      = (const float*)d_in[0];
    const float* W_emb  = (const float*)d_in[1];
    const float* b_emb  = (const float*)d_in[2];
    const float* st_W1  = (const float*)d_in[3];
    const float* st_b1  = (const float*)d_in[4];
    const float* st_W2  = (const float*)d_in[5];
    const float* st_b2  = (const float*)d_in[6];
    const float* at0_W1 = (const float*)d_in[7];
    const float* at0_b1 = (const float*)d_in[8];
    const float* at0_W2 = (const float*)d_in[9];
    const float* at0_b2 = (const float*)d_in[10];
    const float* out_W1 = (const float*)d_in[11];
    const float* out_b1 = (const float*)d_in[12];
    const float* out_W2 = (const float*)d_in[13];
    const float* out_b2 = (const float*)d_in[14];
    float* out = (float*)d_out;

    // JAX keys: key_j = threefry((0,42), (0,j))  [fold_in(_GKEY, j)]
    uint32_t kk0[kJ + 1], kk1[kJ + 1];
    for (int j = 0; j <= kJ; j++)
        tf2x32(0u, 42u, 0u, (uint32_t)j, &kk0[j], &kk1[j]);

    float *p_state, *p_init, *p_new, *p_fin, *p_h;
    cudaGetSymbolAddress((void**)&p_state, g_state);
    cudaGetSymbolAddress((void**)&p_init,  g_init);
    cudaGetSymbolAddress((void**)&p_new,   g_new);
    cudaGetSymbolAddress((void**)&p_fin,   g_fin);
    cudaGetSymbolAddress((void**)&p_h,     g_h);

    const dim3 gemmGrid(kE / 64, kB / 32);  // (4, 32)
    const dim3 blkGrid(kNB, 16);

    // embed: state = x @ W_emb + b_emb  (also save initial_state)
    gemm_kernel<false, true><<<gemmGrid, 256>>>(x, W_emb, b_emb,
                                                p_state, p_init, kB, kIN, kE);
    // initial address (from embed state)
    gemm_kernel<true, false><<<gemmGrid, 256>>>(p_state, at0_W1, at0_b1,
                                                p_h, nullptr, kB, kE, kE);
    addr_kernel<<<kB / 8, 256>>>(p_h, at0_W2, at0_b2, kk0[0], kk1[0], 0);

    for (int i = 0; i < kJ; i++) {
        group_kernel<<<1, kB>>>();
        block_step_kernel<<<blkGrid, 256>>>(st_W1, st_b1, st_W2, st_b2,
                                            p_state, p_new, nullptr, 0);
        gemm_kernel<true, false><<<gemmGrid, 256>>>(p_new, at0_W1, at0_b1,
                                                    p_h, nullptr, kB, kE, kE);
        addr_kernel<<<kB / 8, 256>>>(p_h, at0_W2, at0_b2,
                                     kk0[i + 1], kk1[i + 1], 1);
    }

    // final block step with frozen state/address, + initial_state
    group_kernel<<<1, kB>>>();
    block_step_kernel<<<blkGrid, 256>>>(st_W1, st_b1, st_W2, st_b2,
                                        p_state, p_fin, p_init, 1);
    // output head
    gemm_kernel<true, false><<<gemmGrid, 256>>>(p_fin, out_W1, out_b1,
                                                p_h, nullptr, kB, kE, kE);
    out_kernel<<<kB / 8, 256>>>(p_h, out_W2, out_b2, out);
}